// round 17
// baseline (speedup 1.0000x reference)
#include <cuda_runtime.h>
#include <cstdint>

// Correlation layer: out[b, di*21+dj, h, w] = (1/64) * sum_c f1[b,c,h,w] * f2pad[b,c,h+di,w+dj]
// B=4, C=64, H=W=128, MAX_DISP=10, KS=21 (441 displacements), fp32.
// R16 structure (best: 137.3us) + register double-buffered compute pipeline.

#define B_      4
#define C_      64
#define H_      128
#define W_      128
#define KS_     21
#define PAD_    10

#define HB   2
#define DIB  3
#define CC   8
#define NCHUNK (C_ / CC)   // 8
#define PW   152
#define NROW (HB + DIB - 1)  // 4

#define F2_STRIDE (CC * PW + 4)           // 1220 floats
#define F1A_SIZE  (HB * CC * W_)          // 2048 floats
#define OFF_F1B   (F1A_SIZE + 16)         // 2064: 8256 B ≡ 64 mod 128 -> parity
                                          // fa loads hit disjoint bank quads
#define F1B_SIZE  (F1A_SIZE + 4)          // 2052
#define OFF_C0    (OFF_F1B + F1B_SIZE)    // 4116 floats (16B-aligned)
#define F2_USED   (NROW * F2_STRIDE)      // 4880
#define BUF_FLOATS (OFF_C0 + F2_USED + 12) // 9008 floats = 36032 B
#define SMEM_BYTES (3 * BUF_FLOATS * 4)    // 108096 B per CTA (2 CTAs/SM)

#define NTHREADS 192   // 6 warps = 2 hl * 3 dil; lanes = 16 wg * 2 djp

// ---------------- cp.async helpers ----------------
__device__ __forceinline__ void cp_async16(float* smem_dst, const float* gsrc) {
    uint32_t s = (uint32_t)__cvta_generic_to_shared(smem_dst);
    asm volatile("cp.async.cg.shared.global [%0], [%1], 16;\n" :: "r"(s), "l"(gsrc));
}
__device__ __forceinline__ void cp_async8(float* smem_dst, const float* gsrc) {
    uint32_t s = (uint32_t)__cvta_generic_to_shared(smem_dst);
    asm volatile("cp.async.ca.shared.global [%0], [%1], 8;\n" :: "r"(s), "l"(gsrc));
}
__device__ __forceinline__ void cp_commit() {
    asm volatile("cp.async.commit_group;\n" ::: "memory");
}
template <int N>
__device__ __forceinline__ void cp_wait() {
    asm volatile("cp.async.wait_group %0;\n" :: "n"(N) : "memory");
}

// packed f32x2 fma
__device__ __forceinline__ unsigned long long fma_x2(unsigned long long a,
                                                     unsigned long long b,
                                                     unsigned long long c) {
    unsigned long long d;
    asm("fma.rn.f32x2 %0, %1, %2, %3;" : "=l"(d) : "l"(a), "l"(b), "l"(c));
    return d;
}

// streaming stores (evict-first; output is write-once)
__device__ __forceinline__ void stcs4(float* p, float4 v) {
    asm volatile("st.global.cs.v4.f32 [%0], {%1, %2, %3, %4};"
                 :: "l"(p), "f"(v.x), "f"(v.y), "f"(v.z), "f"(v.w) : "memory");
}
__device__ __forceinline__ void stcs2(float* p, float2 v) {
    asm volatile("st.global.cs.v2.f32 [%0], {%1, %2};"
                 :: "l"(p), "f"(v.x), "f"(v.y) : "memory");
}
__device__ __forceinline__ void stcs1(float* p, float v) {
    asm volatile("st.global.cs.f32 [%0], %1;" :: "l"(p), "f"(v) : "memory");
}

// ---------------- inner compute (register double-buffered) ----------------
// Identical instruction stream for both parities:
//   acc[k][2pc+p] += fa2[p] * fb2[k+p]
// djp=0: fa from f1A -> dj = 2k (k=0..10), w = pb+2p,+1
// djp=1: fa from shifted f1B -> dj = 2k-1 (k=0 junk), w = pb+2p+1,+2
// Loads for channel c+1 are issued BEFORE the FMAs of channel c so the
// 29-cyc LDS latency is covered by ~88 FMA2 issue-cycles within one warp.
// Full unroll -> ptxas renames cur/nxt buffers (no register moves).
__device__ __forceinline__ void compute_chunk(const float* __restrict__ f1p,
                                              const float* __restrict__ f2p,
                                              int pb0,
                                              unsigned long long (&acc)[11][4]) {
#pragma unroll
    for (int pc = 0; pc < 2; pc++) {
        const float* f1q = f1p + pb0 + pc * 64;
        const float* f2q = f2p + pb0 + pc * 64;

        unsigned long long fa2[2];
        unsigned long long fb2[12];
        {
            ulonglong2 fav = *reinterpret_cast<const ulonglong2*>(f1q);
            fa2[0] = fav.x; fa2[1] = fav.y;
            const ulonglong2* fbv = reinterpret_cast<const ulonglong2*>(f2q);
#pragma unroll
            for (int i = 0; i < 6; i++) {
                ulonglong2 t = fbv[i];
                fb2[2 * i] = t.x; fb2[2 * i + 1] = t.y;
            }
        }
#pragma unroll
        for (int c = 0; c < CC; c++) {
            unsigned long long na[2];
            unsigned long long nb[12];
            if (c + 1 < CC) {   // prefetch channel c+1
                ulonglong2 fav = *reinterpret_cast<const ulonglong2*>(f1q + (c + 1) * W_);
                na[0] = fav.x; na[1] = fav.y;
                const ulonglong2* fbv =
                    reinterpret_cast<const ulonglong2*>(f2q + (c + 1) * PW);
#pragma unroll
                for (int i = 0; i < 6; i++) {
                    ulonglong2 t = fbv[i];
                    nb[2 * i] = t.x; nb[2 * i + 1] = t.y;
                }
            }
#pragma unroll
            for (int k = 0; k < 11; k++) {
#pragma unroll
                for (int p = 0; p < 2; p++)
                    acc[k][2 * pc + p] = fma_x2(fa2[p], fb2[k + p], acc[k][2 * pc + p]);
            }
            if (c + 1 < CC) {   // rotate (renamed away by unroll)
                fa2[0] = na[0]; fa2[1] = na[1];
#pragma unroll
                for (int i = 0; i < 12; i++) fb2[i] = nb[i];
            }
        }
    }
}

// ---------------- staging (cp.async, gmem -> smem) ----------------
__device__ __forceinline__ void stage_chunk(const float* __restrict__ f1base,
                                            const float* __restrict__ f2base,
                                            float* buf,
                                            int rlo, int nrows, int tid) {
    {
        const int w4 = tid & 31;
        int hc = tid >> 5;                  // advances by 6
        float* dst0 = buf + w4 * 4;
        const float* src0 = f1base + w4 * 4;
#pragma unroll
        for (int j = 0; j < 3; j++) {
            if (hc < HB * CC) {
                int h = hc >> 3, c = hc & 7;
                cp_async16(dst0 + h * 1024 + c * W_,
                           src0 + c * (H_ * W_) + h * W_);
            }
            hc += 6;
        }
    }
    {
        const int x2 = tid & 63;
        int rc = tid >> 6;                  // advances by 3
        const int rcmax = nrows * 8;
        float* c0 = buf + OFF_C0 + rlo * F2_STRIDE + PAD_ + x2 * 2;
        const float* src0 = f2base + rlo * W_ + x2 * 2;
#pragma unroll
        for (int j = 0; j < 11; j++) {
            if (rc < rcmax) {
                int r = rc >> 3, c = rc & 7;
                cp_async8(c0 + r * F2_STRIDE + c * PW,
                          src0 + c * (H_ * W_) + r * W_);
            }
            rc += 3;
        }
    }
}

// ---------------- f1B build (smem 1-float shift of f1A) ----------------
__device__ __forceinline__ void build_f1b(float* buf, int tid) {
    const float* a0 = buf;
    float* b0 = buf + OFF_F1B;
#pragma unroll
    for (int j = 0; j < 3; j++) {                 // ceil(512/192)
        int i4 = (tid + j * NTHREADS) * 4;
        if (i4 < F1A_SIZE) {
            float4 v = *reinterpret_cast<const float4*>(a0 + i4);
            float nxt = (i4 + 4 < F1A_SIZE) ? a0[i4 + 4] : 0.f;
            *reinterpret_cast<float4*>(b0 + i4) = make_float4(v.y, v.z, v.w, nxt);
        }
    }
}

extern __shared__ float smem[];

__global__ __launch_bounds__(NTHREADS, 2)
void corr_kernel(const float* __restrict__ f1g,
                 const float* __restrict__ f2g,
                 float* __restrict__ out) {
    const int tid  = threadIdx.x;
    const int warp = tid >> 5;
    const int lane = tid & 31;
    const int hl   = warp & 1;
    const int dil  = warp >> 1;
    const int wg   = lane >> 1;
    const int djp  = lane & 1;
    const int pb0  = wg * 4;

    const int b   = blockIdx.z;
    const int h0  = blockIdx.y * HB;
    const int di0 = blockIdx.x * DIB;
    const int r0  = h0 + di0 - PAD_;

    int rlo = (r0 < 0) ? -r0 : 0;
    int rhi = (r0 + NROW > H_) ? (H_ - r0) : NROW;
    if (rhi < rlo) { rlo = 0; rhi = 0; }
    const int nrows = rhi - rlo;

    float* bufA = smem;
    float* bufB = smem + BUF_FLOATS;
    float* bufC = smem + 2 * BUF_FLOATS;

    // one-time zero of f1B + c0 regions in all three buffers
    {
        float4 z = make_float4(0.f, 0.f, 0.f, 0.f);
        const int n4 = (BUF_FLOATS - OFF_F1B) / 4;
        float4* zA = reinterpret_cast<float4*>(bufA + OFF_F1B);
        float4* zB = reinterpret_cast<float4*>(bufB + OFF_F1B);
        float4* zC = reinterpret_cast<float4*>(bufC + OFF_F1B);
        for (int i = tid; i < n4; i += NTHREADS) { zA[i] = z; zB[i] = z; zC[i] = z; }
    }
    __syncthreads();

    const float* f1base = f1g + ((size_t)b * C_ * H_ + h0) * W_;
    const float* f2base = f2g + ((size_t)b * C_ * H_ + r0) * W_;
    const int chunk_gstride = CC * H_ * W_;

    // prologue: stage chunks 0,1; build f1B(0)
    stage_chunk(f1base, f2base, bufA, rlo, nrows, tid);
    cp_commit();
    stage_chunk(f1base + chunk_gstride, f2base + chunk_gstride, bufB, rlo, nrows, tid);
    cp_commit();
    cp_wait<1>();
    __syncthreads();
    build_f1b(bufA, tid);

    unsigned long long acc[11][4];
#pragma unroll
    for (int k = 0; k < 11; k++)
#pragma unroll
        for (int p = 0; p < 4; p++) acc[k][p] = 0ull;
    float accfix = 0.f;   // fused fixup accumulator (djp==1 && wg<5)

    const int f1off = djp * OFF_F1B + hl * (CC * W_);
    const int f2off = OFF_C0 + (hl + dil) * F2_STRIDE;
    const bool fixlane = (djp == 1) && (wg < 5);

    float* p0 = bufA;   // compute chunk cc
    float* p1 = bufB;   // build f1B for chunk cc+1
    float* p2 = bufC;   // stage chunk cc+2

    for (int cc = 0; cc < NCHUNK; cc++) {
        cp_wait<0>();          // drain S(cc+1) (only group in flight)
        __syncthreads();       // staging + f1B(cc) visible; p2's readers done

        if (cc + 2 < NCHUNK) {
            stage_chunk(f1base + (size_t)(cc + 2) * chunk_gstride,
                        f2base + (size_t)(cc + 2) * chunk_gstride,
                        p2, rlo, nrows, tid);
            cp_commit();
        }
        if (cc + 1 < NCHUNK) build_f1b(p1, tid);

        compute_chunk(p0 + f1off, p0 + f2off, pb0, acc);

        // fused fixup: out[b, di*21+(2t+11), h, 0] needs
        // sum_c f1[b,c,h,0] * c0row[2t+11]; zeroed OOB rows make the guard free.
        if (fixlane) {
            const float* fa0 = p0 + hl * (CC * W_);          // f1A (unshifted)
            const float* fb0 = p0 + f2off + 11 + 2 * wg;     // t = wg
#pragma unroll
            for (int c = 0; c < CC; c++)
                accfix = fmaf(fa0[c * W_], fb0[c * PW], accfix);
        }

        float* t = p0; p0 = p1; p1 = p2; p2 = t;   // rotate
    }

    // ---- epilogue (streaming stores) ----
    const float inv = 1.0f / 64.0f;
    const int di = di0 + dil;
    const int h  = h0 + hl;
    float* ob = out + (((size_t)b * (KS_ * KS_) + di * KS_) * H_ + h) * W_;

    if (djp == 0) {
        for (int k = 0; k < 11; k++) {
            float* o = ob + (size_t)(2 * k) * (H_ * W_);
#pragma unroll
            for (int pc = 0; pc < 2; pc++) {
                float2 f0 = *reinterpret_cast<float2*>(&acc[k][2 * pc]);
                float2 f1v = *reinterpret_cast<float2*>(&acc[k][2 * pc + 1]);
                stcs4(o + pb0 + pc * 64,
                      make_float4(f0.x * inv, f0.y * inv, f1v.x * inv, f1v.y * inv));
            }
        }
    } else {
        for (int k = 1; k < 11; k++) {
            float* o = ob + (size_t)(2 * k - 1) * (H_ * W_);
#pragma unroll
            for (int pc = 0; pc < 2; pc++) {
                const int pb = pb0 + pc * 64;
                float2 f0 = *reinterpret_cast<float2*>(&acc[k][2 * pc]);
                float2 f1v = *reinterpret_cast<float2*>(&acc[k][2 * pc + 1]);
                stcs1(o + pb + 1, f0.x * inv);
                stcs2(o + pb + 2, make_float2(f0.y * inv, f1v.x * inv));
                if (pb + 4 < W_) stcs1(o + pb + 4, f1v.y * inv);
            }
        }
        if (wg < 5) {
            // w=0, odd dj: dj=2wg+1 (<10) is padding-zero; dj=2wg+11 from accfix
            stcs1(ob + (size_t)(2 * wg + 1) * (H_ * W_), 0.f);
            stcs1(ob + (size_t)(2 * wg + 11) * (H_ * W_), accfix * inv);
        }
    }
}

extern "C" void kernel_launch(void* const* d_in, const int* in_sizes, int n_in,
                              void* d_out, int out_size) {
    const float* f1 = (const float*)d_in[0];
    const float* f2 = (const float*)d_in[1];
    float* out = (float*)d_out;

    cudaFuncSetAttribute(corr_kernel, cudaFuncAttributeMaxDynamicSharedMemorySize,
                         SMEM_BYTES);

    dim3 grid(KS_ / DIB, H_ / HB, B_);   // (7, 64, 4) = 1792 CTAs
    corr_kernel<<<grid, NTHREADS, SMEM_BYTES>>>(f1, f2, out);
}